// round 14
// baseline (speedup 1.0000x reference)
#include <cuda_runtime.h>
#include <cuda_fp16.h>
#include <cstdint>

// dims
#define B_ 64
#define N_ 32
#define F_ 16
#define S_ 8
#define C_ 128
#define H_ 256
#define D_ 256
#define OBS_STRIDE 9728
#define A_OFF 512        // N_*F_
#define E_OFF 1536       // N_*F_ + N_*N_
#define ROWS 2048        // B_*N_
#define EDGES 65536      // max edges
#define KAUG2 4160       // G2 K: 4096 (h,f) + 16 bk-ones + 16 X + 1 const + 31 pad
#define KCH2 130         // KAUG2/32 chunks
#define KSPLIT 16
#define ASTR 40          // smem tile k-stride (fp16), 32 + 8 pad (LDSM conflict-free)

// warp-level fp16 MMA, fp32 accum (HMMA; compiles for compute_103)
#define MMA_F16(c, a, b0v, b1v)                                         \
    asm volatile(                                                       \
        "mma.sync.aligned.m16n8k16.row.col.f32.f16.f16.f32 "            \
        "{%0,%1,%2,%3}, {%4,%5,%6,%7}, {%8,%9}, {%0,%1,%2,%3};"         \
        : "+f"((c)[0]), "+f"((c)[1]), "+f"((c)[2]), "+f"((c)[3])        \
        : "r"((a)[0]), "r"((a)[1]), "r"((a)[2]), "r"((a)[3]),           \
          "r"(b0v), "r"(b1v))

#define LDSM_X4(r0, r1, r2, r3, addr)                                   \
    asm volatile(                                                       \
        "ldmatrix.sync.aligned.m8n8.x4.shared.b16 {%0,%1,%2,%3}, [%4];" \
        : "=r"(r0), "=r"(r1), "=r"(r2), "=r"(r3) : "r"(addr))

// async copy (Ampere+): 16B global->shared, fire-and-forget
#define CP16(dst, src)                                                  \
    asm volatile("cp.async.ca.shared.global [%0], [%1], 16;"            \
                 :: "r"(dst), "l"(src))
#define CP_COMMIT() asm volatile("cp.async.commit_group;" ::: "memory")
#define CP_WAIT(n)  asm volatile("cp.async.wait_group %0;" :: "n"(n) : "memory")

__device__ __forceinline__ uint32_t smem_u32(const void* p) {
    uint32_t a;
    asm("{ .reg .u64 t; cvta.to.shared.u64 t, %1; cvt.u32.u64 %0, t; }"
        : "=r"(a) : "l"(p));
    return a;
}

// exact fp16 hi+lo split (A-side operands)
__device__ __forceinline__ void hsplit(float x, __half& h, __half& l) {
    h = __float2half(x);
    l = __float2half(x - __half2float(h));
}

// ---------------------------------------------------------------------------
// static scratch
// ---------------------------------------------------------------------------
__device__ __align__(16) __half g_W2Th[H_ * H_];      // W2T[c][k], fp16
__device__ __align__(16) __half g_B2h[C_ * KAUG2];    // B2[c][kk], fp16
__device__ __align__(16) __half g_h1hi[(size_t)EDGES * H_];
__device__ __align__(16) __half g_h1lo[(size_t)EDGES * H_];
__device__ __align__(16) float g_h2[(size_t)EDGES * H_];
__device__ __align__(16) __half g_A2hi[(size_t)ROWS * KAUG2];
__device__ __align__(16) __half g_A2lo[(size_t)ROWS * KAUG2];
__device__ __align__(16) float g_P[KSPLIT * ROWS * C_];
__device__ int g_cnt[ROWS];
__device__ int g_rowStart[ROWS];
__device__ int g_eSrc[EDGES];
__device__ int g_eRow[EDGES];
__device__ int g_meta[4];   // [0]=total, [1]=padTotal, [2]=ntiles

// smem: 2 stages x 3 tiles x (128 x 40 fp16 = 10240B) = 61440B (2 CTAs/SM)
#define TILE_B 10240
#define STAGE_B (3 * TILE_B)
#define MMA_SMEM_BYTES (2 * STAGE_B)

// ---------------------------------------------------------------------------
// prep: W2T fp16 + augmented B2 (Wk | bk | Wroot | bconv | 0) fp16
// ---------------------------------------------------------------------------
__global__ void prep_kernel(const float* __restrict__ W2,
                            const float* __restrict__ Wk,
                            const float* __restrict__ bk,
                            const float* __restrict__ Wroot,
                            const float* __restrict__ bconv) {
    int t = blockIdx.x * 256 + threadIdx.x;
    if (t < H_ * H_) {
        int c = t >> 8, k = t & 255;
        g_W2Th[t] = __float2half(W2[k * H_ + c]);
    }
    if (t < C_ * KAUG2) {
        int c = t / KAUG2, kk = t % KAUG2;
        float v = 0.0f;
        if (kk < 4096) v = Wk[(kk >> 4) * (C_ * F_) + c * F_ + (kk & 15)];
        else if (kk < 4112) v = bk[c * F_ + (kk - 4096)];
        else if (kk < 4128) v = Wroot[(kk - 4112) * C_ + c];
        else if (kk == 4128) v = bconv[c];
        g_B2h[t] = __float2half(v);
    }
}

// ---------------------------------------------------------------------------
// count + scan (single CTA, 1024 thr, 2 rows each)
// ---------------------------------------------------------------------------
__global__ void __launch_bounds__(1024) count_scan_kernel(const float* __restrict__ obs) {
    __shared__ int sA[1024], sB[1024];
    const int t = threadIdx.x;
    int c0 = 0, c1 = 0;
    {
        const int r0 = 2 * t, r1 = 2 * t + 1;
        const float* a0 = obs + (size_t)(r0 >> 5) * OBS_STRIDE + A_OFF + (r0 & 31) * N_;
        const float* a1 = obs + (size_t)(r1 >> 5) * OBS_STRIDE + A_OFF + (r1 & 31) * N_;
#pragma unroll 8
        for (int i = 0; i < N_; i++) {
            c0 += (a0[i] != 0.0f);
            c1 += (a1[i] != 0.0f);
        }
    }
    g_cnt[2 * t] = c0;
    g_cnt[2 * t + 1] = c1;
    const int pair = c0 + c1;
    sA[t] = pair;
    __syncthreads();
    int* src = sA;
    int* dst = sB;
    for (int off = 1; off < 1024; off <<= 1) {
        int v = src[t] + (t >= off ? src[t - off] : 0);
        dst[t] = v;
        __syncthreads();
        int* tmp = src; src = dst; dst = tmp;
    }
    const int inc = src[t];
    const int excl = inc - pair;
    g_rowStart[2 * t] = excl;
    g_rowStart[2 * t + 1] = excl + c0;
    if (t == 1023) {
        int total = inc;
        int ntiles = (total + 127) >> 7;
        g_meta[0] = total;
        g_meta[1] = ntiles << 7;
        g_meta[2] = ntiles;
    }
}

// ---------------------------------------------------------------------------
// fill: compact edge list (deterministic ballot order)
// ---------------------------------------------------------------------------
__global__ void __launch_bounds__(256) fill_kernel(const float* __restrict__ obs) {
    const int b = blockIdx.x;
    const int wid = threadIdx.x >> 5, lane = threadIdx.x & 31;
    const float* orow = obs + (size_t)b * OBS_STRIDE;
    for (int j = wid; j < N_; j += 8) {
        const int row = b * N_ + j;
        float a = orow[A_OFF + j * N_ + lane];
        unsigned m = __ballot_sync(0xffffffffu, a != 0.0f);
        int pos = __popc(m & ((1u << lane) - 1u));
        if (a != 0.0f) {
            int s = g_rowStart[row] + pos;
            g_eSrc[s] = lane;
            g_eRow[s] = row;
        }
    }
}

// ---------------------------------------------------------------------------
// h1: grid (512 tiles, 8 eighths) — 16 slots per CTA, thread = k
// ---------------------------------------------------------------------------
__global__ void __launch_bounds__(256) h1_kernel(const float* __restrict__ obs,
                                                 const float* __restrict__ W1,
                                                 const float* __restrict__ b1) {
    __shared__ float Es[16 * S_];
    const int tile = blockIdx.x;
    if (tile >= g_meta[2]) return;
    const int total = g_meta[0];
    const int base = (tile << 7) + blockIdx.y * 16;
    int limit = total - base;
    if (limit > 16) limit = 16;
    if (limit < 0) limit = 0;
    const int tid = threadIdx.x;

    if (tid < 32) {
        const int slot = tid >> 1, q = (tid & 1) * 4;
        float4 v = make_float4(0.f, 0.f, 0.f, 0.f);
        if (slot < limit) {
            const int gs = base + slot;
            const int row = g_eRow[gs], i = g_eSrc[gs];
            const int b = row >> 5, j = row & 31;
            v = *reinterpret_cast<const float4*>(
                obs + (size_t)b * OBS_STRIDE + E_OFF + (size_t)(j * N_ + i) * S_ + q);
        }
        *reinterpret_cast<float4*>(&Es[slot * S_ + q]) = v;
    }
    __syncthreads();

    const int k = tid;
    float w1r[S_];
#pragma unroll
    for (int s = 0; s < S_; s++) w1r[s] = __ldg(&W1[s * H_ + k]);
    const float b1k = __ldg(&b1[k]);

#pragma unroll
    for (int e = 0; e < 16; e++) {
        float acc = b1k;
#pragma unroll
        for (int s = 0; s < S_; s++) acc += Es[e * S_ + s] * w1r[s];
        acc = (e < limit) ? fmaxf(acc, 0.0f) : 0.0f;
        __half h, l;
        hsplit(acc, h, l);
        const size_t o = (size_t)(base + e) * H_ + k;
        g_h1hi[o] = h;
        g_h1lo[o] = l;
    }
}

// ---------------------------------------------------------------------------
// shared MMA chunk body (K=32, ldmatrix, fp16 2-pass: (Ahi+Alo) @ Bh)
// ---------------------------------------------------------------------------
__device__ __forceinline__ void mma_chunk32(
    float acc[2][8][4], uint32_t stageBase, int warpM, int warpN, int lane) {
    const int lt = lane >> 3, lr = lane & 7;
    const uint32_t sAh = stageBase, sAl = stageBase + TILE_B;
    const uint32_t sBh = stageBase + 2 * TILE_B;
    uint32_t aOff[2];
#pragma unroll
    for (int m = 0; m < 2; m++) {
        const int row = warpM * 32 + m * 16 + ((lt & 1) << 3) + lr;
        aOff[m] = (uint32_t)(row * ASTR + ((lt >> 1) << 3)) * 2;
    }
    uint32_t bOff[4];
#pragma unroll
    for (int nb = 0; nb < 4; nb++) {
        const int n = warpN * 64 + nb * 16 + ((lt >> 1) << 3) + lr;
        bOff[nb] = (uint32_t)(n * ASTR + ((lt & 1) << 3)) * 2;
    }

#pragma unroll
    for (int kw = 0; kw < 32; kw += 16) {
        uint32_t ah[2][4], al[2][4];
#pragma unroll
        for (int m = 0; m < 2; m++) {
            LDSM_X4(ah[m][0], ah[m][1], ah[m][2], ah[m][3], sAh + aOff[m] + kw * 2);
            LDSM_X4(al[m][0], al[m][1], al[m][2], al[m][3], sAl + aOff[m] + kw * 2);
        }
#pragma unroll
        for (int nb = 0; nb < 4; nb++) {
            uint32_t bh[4];
            LDSM_X4(bh[0], bh[1], bh[2], bh[3], sBh + bOff[nb] + kw * 2);
#pragma unroll
            for (int m = 0; m < 2; m++) {
                MMA_F16(acc[m][2 * nb + 0], ah[m], bh[0], bh[1]);
                MMA_F16(acc[m][2 * nb + 0], al[m], bh[0], bh[1]);
                MMA_F16(acc[m][2 * nb + 1], ah[m], bh[2], bh[3]);
                MMA_F16(acc[m][2 * nb + 1], al[m], bh[2], bh[3]);
            }
        }
    }
}

// ---------------------------------------------------------------------------
// G1: h2 = relu(h1 @ W2T^T + b2); cp.async double-buffered, K-chunk 32 (8 ch)
// grid (512 tiles, 2 col-tiles), 256 thr = 8 warps (4Mx2N)
// ---------------------------------------------------------------------------
__global__ void __launch_bounds__(256, 2) g1_mma_kernel(const float* __restrict__ b2) {
    extern __shared__ __align__(16) __half smem[];
    const int tile = blockIdx.x;
    if (tile >= g_meta[2]) return;
    const int c0 = blockIdx.y * 128;
    const int tid = threadIdx.x, wid = tid >> 5, lane = tid & 31;
    const int warpM = wid & 3, warpN = wid >> 2;
    const int g = lane >> 2, tig = lane & 3;
    const uint32_t sb = smem_u32(smem);
    const size_t abase = (size_t)tile * 128 * H_;

    auto load = [&](int ch, int st) {
        const int k0 = ch * 32;
        const uint32_t sbase = sb + st * STAGE_B;
#pragma unroll
        for (int l = 0; l < 2; l++) {
            const int cc = l * 256 + tid;       // 0..511
            const int r = cc >> 2, kq = (cc & 3) * 8;
            const uint32_t d = sbase + (uint32_t)(r * ASTR + kq) * 2;
            CP16(d + 0 * TILE_B, g_h1hi + abase + (size_t)r * H_ + k0 + kq);
            CP16(d + 1 * TILE_B, g_h1lo + abase + (size_t)r * H_ + k0 + kq);
            CP16(d + 2 * TILE_B, g_W2Th + (size_t)(c0 + r) * H_ + k0 + kq);
        }
    };

    float acc[2][8][4];
#pragma unroll
    for (int m = 0; m < 2; m++)
#pragma unroll
        for (int n = 0; n < 8; n++)
#pragma unroll
            for (int q = 0; q < 4; q++) acc[m][n][q] = 0.0f;

    load(0, 0);
    CP_COMMIT();
    int stage = 0;
#pragma unroll 1
    for (int ch = 0; ch < 8; ch++) {
        if (ch + 1 < 8) {
            load(ch + 1, stage ^ 1);
            CP_COMMIT();
            CP_WAIT(1);
        } else {
            CP_WAIT(0);
        }
        __syncthreads();
        mma_chunk32(acc, sb + stage * STAGE_B, warpM, warpN, lane);
        __syncthreads();
        stage ^= 1;
    }

#pragma unroll
    for (int n = 0; n < 8; n++) {
        const int col = c0 + warpN * 64 + n * 8 + tig * 2;
        const float bias0 = __ldg(&b2[col]), bias1 = __ldg(&b2[col + 1]);
#pragma unroll
        for (int m = 0; m < 2; m++) {
            const int r0 = tile * 128 + warpM * 32 + m * 16 + g;
            float2 v0 = make_float2(fmaxf(acc[m][n][0] + bias0, 0.0f),
                                    fmaxf(acc[m][n][1] + bias1, 0.0f));
            float2 v1 = make_float2(fmaxf(acc[m][n][2] + bias0, 0.0f),
                                    fmaxf(acc[m][n][3] + bias1, 0.0f));
            *reinterpret_cast<float2*>(&g_h2[(size_t)r0 * H_ + col]) = v0;
            *reinterpret_cast<float2*>(&g_h2[(size_t)(r0 + 8) * H_ + col]) = v1;
        }
    }
}

// ---------------------------------------------------------------------------
// fold: A2[row] = [ M(h,f) | sumX (bk) | X (Wroot) | 1 (bconv) | 0 ]
// grid 2048 rows, 256 thr (thread = h); 4-wide h2 prefetch
// ---------------------------------------------------------------------------
__global__ void __launch_bounds__(256) fold_kernel(const float* __restrict__ obs) {
    __shared__ float Xs[N_ * F_];
    __shared__ int idx[N_];
    __shared__ int s_start, s_cnt;
    const int row = blockIdx.x;
    const int b = row >> 5, j = row & 31;
    const int k = threadIdx.x;
    const float* orow = obs + (size_t)b * OBS_STRIDE;

    if (k == 0) {
        s_start = g_rowStart[row];
        s_cnt = g_cnt[row];
    }
    for (int t = k; t < N_ * F_; t += 256) Xs[t] = orow[t];
    __syncthreads();
    const int cnt = s_cnt, start = s_start;
    if (k < cnt) idx[k] = g_eSrc[start + k];
    __syncthreads();

    float M[F_];
#pragma unroll
    for (int f = 0; f < F_; f++) M[f] = 0.0f;

    const float* h2p = g_h2 + (size_t)start * H_ + k;
    int e = 0;
    for (; e + 4 <= cnt; e += 4) {
        const float v0 = h2p[(size_t)(e + 0) * H_];
        const float v1 = h2p[(size_t)(e + 1) * H_];
        const float v2 = h2p[(size_t)(e + 2) * H_];
        const float v3 = h2p[(size_t)(e + 3) * H_];
        const int i0 = idx[e], i1 = idx[e + 1], i2 = idx[e + 2], i3 = idx[e + 3];
#pragma unroll
        for (int f = 0; f < F_; f++) {
            M[f] += v0 * Xs[i0 * F_ + f];
            M[f] += v1 * Xs[i1 * F_ + f];
            M[f] += v2 * Xs[i2 * F_ + f];
            M[f] += v3 * Xs[i3 * F_ + f];
        }
    }
    for (; e < cnt; e++) {
        const float h2v = h2p[(size_t)e * H_];
        const int i = idx[e];
#pragma unroll
        for (int f = 0; f < F_; f++) M[f] += h2v * Xs[i * F_ + f];
    }

    __align__(16) __half hi[F_], lo[F_];
#pragma unroll
    for (int f = 0; f < F_; f++) hsplit(M[f], hi[f], lo[f]);
    {
        const size_t o = (size_t)row * KAUG2 + k * F_;
        reinterpret_cast<uint4*>(g_A2hi + o)[0] = reinterpret_cast<uint4*>(hi)[0];
        reinterpret_cast<uint4*>(g_A2hi + o)[1] = reinterpret_cast<uint4*>(hi)[1];
        reinterpret_cast<uint4*>(g_A2lo + o)[0] = reinterpret_cast<uint4*>(lo)[0];
        reinterpret_cast<uint4*>(g_A2lo + o)[1] = reinterpret_cast<uint4*>(lo)[1];
    }

    // augmented tail: sumX (kk 4096..4111), X (4112..4127), 1.0 (4128), 0 pad
    if (k < 16) {
        float ssum = 0.0f;
        for (int ee = 0; ee < cnt; ee++) ssum += Xs[idx[ee] * F_ + k];
        __half h, l;
        hsplit(ssum, h, l);
        g_A2hi[(size_t)row * KAUG2 + 4096 + k] = h;
        g_A2lo[(size_t)row * KAUG2 + 4096 + k] = l;
    } else if (k < 32) {
        __half h, l;
        hsplit(Xs[j * F_ + (k - 16)], h, l);
        g_A2hi[(size_t)row * KAUG2 + 4096 + k] = h;
        g_A2lo[(size_t)row * KAUG2 + 4096 + k] = l;
    } else if (k == 32) {
        g_A2hi[(size_t)row * KAUG2 + 4128] = __float2half(1.0f);
        g_A2lo[(size_t)row * KAUG2 + 4128] = __float2half(0.0f);
    } else if (k < 64) {
        g_A2hi[(size_t)row * KAUG2 + 4096 + k] = __float2half(0.0f);
        g_A2lo[(size_t)row * KAUG2 + 4096 + k] = __float2half(0.0f);
    }
}

// ---------------------------------------------------------------------------
// G2: P[s] partial of A2[2048,4160] @ B2^T; cp.async double-buffered, K-chunk 32
// grid (16 row-tiles, 16 splits) = 256 CTAs, 2 CTAs/SM
// ---------------------------------------------------------------------------
__global__ void __launch_bounds__(256, 2) g2_mma_kernel() {
    extern __shared__ __align__(16) __half smem[];
    const int r0 = blockIdx.x * 128;
    const int s = blockIdx.y;
    const int tid = threadIdx.x, wid = tid >> 5, lane = tid & 31;
    const int warpM = wid & 3, warpN = wid >> 2;
    const int g = lane >> 2, tig = lane & 3;
    const uint32_t sb = smem_u32(smem);

    auto load = [&](int ch, int st) {
        const int k0 = ch * 32;
        const uint32_t sbase = sb + st * STAGE_B;
#pragma unroll
        for (int l = 0; l < 2; l++) {
            const int cc = l * 256 + tid;
            const int r = cc >> 2, kq = (cc & 3) * 8;
            const uint32_t d = sbase + (uint32_t)(r * ASTR + kq) * 2;
            CP16(d + 0 * TILE_B, g_A2hi + (size_t)(r0 + r) * KAUG2 + k0 + kq);
            CP16(d + 1 * TILE_B, g_A2lo + (size_t)(r0 + r) * KAUG2 + k0 + kq);
            CP16(d + 2 * TILE_B, g_B2h + (size_t)r * KAUG2 + k0 + kq);
        }
    };

    float acc[2][8][4];
#pragma unroll
    for (int m = 0; m < 2; m++)
#pragma unroll
        for (int n = 0; n < 8; n++)
#pragma unroll
            for (int q = 0; q < 4; q++) acc[m][n][q] = 0.0f;

    int ch = s;
    load(ch, 0);
    CP_COMMIT();
    int stage = 0;
#pragma unroll 1
    while (true) {
        const int chn = ch + KSPLIT;
        const bool more = (chn < KCH2);
        if (more) {
            load(chn, stage ^ 1);
            CP_COMMIT();
            CP_WAIT(1);
        } else {
            CP_WAIT(0);
        }
        __syncthreads();
        mma_chunk32(acc, sb + stage * STAGE_B, warpM, warpN, lane);
        if (!more) break;
        __syncthreads();
        ch = chn;
        stage ^= 1;
    }

#pragma unroll
    for (int n = 0; n < 8; n++) {
        const int col = warpN * 64 + n * 8 + tig * 2;
#pragma unroll
        for (int m = 0; m < 2; m++) {
            const int rr = r0 + warpM * 32 + m * 16 + g;
            float2 v0 = make_float2(acc[m][n][0], acc[m][n][1]);
            float2 v1 = make_float2(acc[m][n][2], acc[m][n][3]);
            *reinterpret_cast<float2*>(&g_P[((size_t)s * ROWS + rr) * C_ + col]) = v0;
            *reinterpret_cast<float2*>(&g_P[((size_t)s * ROWS + rr + 8) * C_ + col]) = v1;
        }
    }
}

// ---------------------------------------------------------------------------
// phase3: reduce splits -> Xc (relu), attention softmax pool, dense tanh
// ---------------------------------------------------------------------------
__global__ void __launch_bounds__(256) phase3_kernel(
    const float* __restrict__ attn_w,
    const float* __restrict__ Wd,
    const float* __restrict__ bd,
    float* __restrict__ out) {
    __shared__ __align__(16) float Xc[N_][C_];
    __shared__ float attn[N_];
    __shared__ float logits[N_];
    __shared__ float pooled[C_];

    const int b = blockIdx.x;
    const int tid = threadIdx.x;

    for (int t = tid; t < N_ * C_; t += 256) {
        const int j = t >> 7, c = t & 127;
        const int row = b * N_ + j;
        float sum = 0.0f;
#pragma unroll
        for (int s = 0; s < KSPLIT; s++)
            sum += g_P[((size_t)s * ROWS + row) * C_ + c];
        Xc[j][c] = fmaxf(sum, 0.0f);
    }
    __syncthreads();

    const int w = tid >> 5, lane = tid & 31;
    const float aw0 = attn_w[lane], aw1 = attn_w[lane + 32];
    const float aw2 = attn_w[lane + 64], aw3 = attn_w[lane + 96];
    for (int j = w * 4; j < w * 4 + 4; j++) {
        float p = Xc[j][lane] * aw0 + Xc[j][lane + 32] * aw1 +
                  Xc[j][lane + 64] * aw2 + Xc[j][lane + 96] * aw3;
#pragma unroll
        for (int off = 16; off; off >>= 1) p += __shfl_xor_sync(0xffffffffu, p, off);
        if (lane == 0) logits[j] = p;
    }
    __syncthreads();

    if (tid < 32) {
        float l = logits[tid];
        float m = l;
#pragma unroll
        for (int off = 16; off; off >>= 1)
            m = fmaxf(m, __shfl_xor_sync(0xffffffffu, m, off));
        float e = expf(l - m);
        float ssum = e;
#pragma unroll
        for (int off = 16; off; off >>= 1) ssum += __shfl_xor_sync(0xffffffffu, ssum, off);
        attn[tid] = e / ssum;
    }
    __syncthreads();

    if (tid < C_) {
        float pc = 0.0f;
#pragma unroll
        for (int j = 0; j < N_; j++) pc += attn[j] * Xc[j][tid];
        pooled[tid] = pc;
    }
    __syncthreads();

    float sum = bd[tid];
#pragma unroll 8
    for (int cc = 0; cc < C_; cc++) sum += pooled[cc] * Wd[cc * D_ + tid];
    out[(size_t)b * D_ + tid] = tanhf(sum);
}

// ---------------------------------------------------------------------------
extern "C" void kernel_launch(void* const* d_in, const int* in_sizes, int n_in,
                              void* d_out, int out_size) {
    const float* obs    = (const float*)d_in[0];
    const float* W1     = (const float*)d_in[1];
    const float* b1     = (const float*)d_in[2];
    const float* W2     = (const float*)d_in[3];
    const float* b2     = (const float*)d_in[4];
    const float* Wk     = (const float*)d_in[5];
    const float* bk     = (const float*)d_in[6];
    const float* Wroot  = (const float*)d_in[7];
    const float* bconv  = (const float*)d_in[8];
    const float* attn_w = (const float*)d_in[9];
    const float* Wd     = (const float*)d_in[10];
    const float* bd     = (const float*)d_in[11];
    float* out = (float*)d_out;

    cudaFuncSetAttribute(g1_mma_kernel,
                         cudaFuncAttributeMaxDynamicSharedMemorySize, MMA_SMEM_BYTES);
    cudaFuncSetAttribute(g2_mma_kernel,
                         cudaFuncAttributeMaxDynamicSharedMemorySize, MMA_SMEM_BYTES);

    prep_kernel<<<(C_ * KAUG2 + 255) / 256, 256>>>(W2, Wk, bk, Wroot, bconv);
    count_scan_kernel<<<1, 1024>>>(obs);
    fill_kernel<<<B_, 256>>>(obs);
    h1_kernel<<<dim3(512, 8), 256>>>(obs, W1, b1);
    g1_mma_kernel<<<dim3(512, 2), 256, MMA_SMEM_BYTES>>>(b2);
    fold_kernel<<<ROWS, 256>>>(obs);
    g2_mma_kernel<<<dim3(16, KSPLIT), 256, MMA_SMEM_BYTES>>>();
    phase3_kernel<<<B_, 256>>>(attn_w, Wd, bd, out);
}

// round 15
// speedup vs baseline: 1.4638x; 1.4638x over previous
#include <cuda_runtime.h>
#include <cuda_fp16.h>
#include <cstdint>

// dims
#define B_ 64
#define N_ 32
#define F_ 16
#define S_ 8
#define C_ 128
#define H_ 256
#define D_ 256
#define OBS_STRIDE 9728
#define A_OFF 512        // N_*F_
#define E_OFF 1536       // N_*F_ + N_*N_
#define ROWS 2048        // B_*N_
#define EDGES 65536      // max edges
#define KAUG2 4160       // G2 K: 4096 (h,f) + 16 bk-ones + 16 X + 1 const + 31 pad
#define KCH2 130         // KAUG2/32 chunks
#define KSPLIT 16
#define ASTR 40          // smem tile k-stride (fp16), 32 + 8 pad (LDSM conflict-free)

// warp-level fp16 MMA, fp32 accum (HMMA; compiles for compute_103)
#define MMA_F16(c, a, b0v, b1v)                                         \
    asm volatile(                                                       \
        "mma.sync.aligned.m16n8k16.row.col.f32.f16.f16.f32 "            \
        "{%0,%1,%2,%3}, {%4,%5,%6,%7}, {%8,%9}, {%0,%1,%2,%3};"         \
        : "+f"((c)[0]), "+f"((c)[1]), "+f"((c)[2]), "+f"((c)[3])        \
        : "r"((a)[0]), "r"((a)[1]), "r"((a)[2]), "r"((a)[3]),           \
          "r"(b0v), "r"(b1v))

#define LDSM_X4(r0, r1, r2, r3, addr)                                   \
    asm volatile(                                                       \
        "ldmatrix.sync.aligned.m8n8.x4.shared.b16 {%0,%1,%2,%3}, [%4];" \
        : "=r"(r0), "=r"(r1), "=r"(r2), "=r"(r3) : "r"(addr))

// async copy (Ampere+): 16B global->shared, fire-and-forget
#define CP16(dst, src)                                                  \
    asm volatile("cp.async.ca.shared.global [%0], [%1], 16;"            \
                 :: "r"(dst), "l"(src))
#define CP_COMMIT() asm volatile("cp.async.commit_group;" ::: "memory")
#define CP_WAIT(n)  asm volatile("cp.async.wait_group %0;" :: "n"(n) : "memory")

__device__ __forceinline__ uint32_t smem_u32(const void* p) {
    uint32_t a;
    asm("{ .reg .u64 t; cvta.to.shared.u64 t, %1; cvt.u32.u64 %0, t; }"
        : "=r"(a) : "l"(p));
    return a;
}

// flush values below fp16 min-normal to zero (denormal-free fp16 operands)
__device__ __forceinline__ float dnflush(float x) {
    return (fabsf(x) < 6.104e-5f) ? 0.0f : x;
}
// fp16 hi+lo split, both denormal-free
__device__ __forceinline__ void hsplit(float x, __half& h, __half& l) {
    x = dnflush(x);
    h = __float2half(x);
    l = __float2half(dnflush(x - __half2float(h)));
}

// ---------------------------------------------------------------------------
// static scratch
// ---------------------------------------------------------------------------
__device__ __align__(16) __half g_W2Th[H_ * H_];      // W2T[c][k], fp16
__device__ __align__(16) __half g_B2h[C_ * KAUG2];    // B2[c][kk], fp16
__device__ __align__(16) __half g_h1hi[(size_t)EDGES * H_];
__device__ __align__(16) __half g_h1lo[(size_t)EDGES * H_];
__device__ __align__(16) float g_h2[(size_t)EDGES * H_];
__device__ __align__(16) __half g_A2hi[(size_t)ROWS * KAUG2];
__device__ __align__(16) __half g_A2lo[(size_t)ROWS * KAUG2];
__device__ __align__(16) float g_P[KSPLIT * ROWS * C_];
__device__ int g_cnt[ROWS];
__device__ int g_rowStart[ROWS];
__device__ int g_eSrc[EDGES];
__device__ int g_eRow[EDGES];
__device__ int g_meta[4];   // [0]=total, [1]=padTotal, [2]=ntiles

// smem: 2 stages x 3 tiles x (128 x 40 fp16 = 10240B) = 61440B (2 CTAs/SM)
#define TILE_B 10240
#define STAGE_B (3 * TILE_B)
#define MMA_SMEM_BYTES (2 * STAGE_B)

// ---------------------------------------------------------------------------
// prep: W2T fp16 + augmented B2 (Wk | bk | Wroot | bconv | 0) fp16, flushed
// ---------------------------------------------------------------------------
__global__ void prep_kernel(const float* __restrict__ W2,
                            const float* __restrict__ Wk,
                            const float* __restrict__ bk,
                            const float* __restrict__ Wroot,
                            const float* __restrict__ bconv) {
    int t = blockIdx.x * 256 + threadIdx.x;
    if (t < H_ * H_) {
        int c = t >> 8, k = t & 255;
        g_W2Th[t] = __float2half(dnflush(W2[k * H_ + c]));
    }
    if (t < C_ * KAUG2) {
        int c = t / KAUG2, kk = t % KAUG2;
        float v = 0.0f;
        if (kk < 4096) v = Wk[(kk >> 4) * (C_ * F_) + c * F_ + (kk & 15)];
        else if (kk < 4112) v = bk[c * F_ + (kk - 4096)];
        else if (kk < 4128) v = Wroot[(kk - 4112) * C_ + c];
        else if (kk == 4128) v = bconv[c];
        g_B2h[t] = __float2half(dnflush(v));
    }
}

// ---------------------------------------------------------------------------
// count + scan (single CTA, 1024 thr, 2 rows each)
// ---------------------------------------------------------------------------
__global__ void __launch_bounds__(1024) count_scan_kernel(const float* __restrict__ obs) {
    __shared__ int sA[1024], sB[1024];
    const int t = threadIdx.x;
    int c0 = 0, c1 = 0;
    {
        const int r0 = 2 * t, r1 = 2 * t + 1;
        const float* a0 = obs + (size_t)(r0 >> 5) * OBS_STRIDE + A_OFF + (r0 & 31) * N_;
        const float* a1 = obs + (size_t)(r1 >> 5) * OBS_STRIDE + A_OFF + (r1 & 31) * N_;
#pragma unroll 8
        for (int i = 0; i < N_; i++) {
            c0 += (a0[i] != 0.0f);
            c1 += (a1[i] != 0.0f);
        }
    }
    g_cnt[2 * t] = c0;
    g_cnt[2 * t + 1] = c1;
    const int pair = c0 + c1;
    sA[t] = pair;
    __syncthreads();
    int* src = sA;
    int* dst = sB;
    for (int off = 1; off < 1024; off <<= 1) {
        int v = src[t] + (t >= off ? src[t - off] : 0);
        dst[t] = v;
        __syncthreads();
        int* tmp = src; src = dst; dst = tmp;
    }
    const int inc = src[t];
    const int excl = inc - pair;
    g_rowStart[2 * t] = excl;
    g_rowStart[2 * t + 1] = excl + c0;
    if (t == 1023) {
        int total = inc;
        int ntiles = (total + 127) >> 7;
        g_meta[0] = total;
        g_meta[1] = ntiles << 7;
        g_meta[2] = ntiles;
    }
}

// ---------------------------------------------------------------------------
// fill: compact edge list (deterministic ballot order)
// ---------------------------------------------------------------------------
__global__ void __launch_bounds__(256) fill_kernel(const float* __restrict__ obs) {
    const int b = blockIdx.x;
    const int wid = threadIdx.x >> 5, lane = threadIdx.x & 31;
    const float* orow = obs + (size_t)b * OBS_STRIDE;
    for (int j = wid; j < N_; j += 8) {
        const int row = b * N_ + j;
        float a = orow[A_OFF + j * N_ + lane];
        unsigned m = __ballot_sync(0xffffffffu, a != 0.0f);
        int pos = __popc(m & ((1u << lane) - 1u));
        if (a != 0.0f) {
            int s = g_rowStart[row] + pos;
            g_eSrc[s] = lane;
            g_eRow[s] = row;
        }
    }
}

// ---------------------------------------------------------------------------
// h1: grid (512 tiles, 8 eighths) — 16 slots per CTA, thread = k
// ---------------------------------------------------------------------------
__global__ void __launch_bounds__(256) h1_kernel(const float* __restrict__ obs,
                                                 const float* __restrict__ W1,
                                                 const float* __restrict__ b1) {
    __shared__ float Es[16 * S_];
    const int tile = blockIdx.x;
    if (tile >= g_meta[2]) return;
    const int total = g_meta[0];
    const int base = (tile << 7) + blockIdx.y * 16;
    int limit = total - base;
    if (limit > 16) limit = 16;
    if (limit < 0) limit = 0;
    const int tid = threadIdx.x;

    if (tid < 32) {
        const int slot = tid >> 1, q = (tid & 1) * 4;
        float4 v = make_float4(0.f, 0.f, 0.f, 0.f);
        if (slot < limit) {
            const int gs = base + slot;
            const int row = g_eRow[gs], i = g_eSrc[gs];
            const int b = row >> 5, j = row & 31;
            v = *reinterpret_cast<const float4*>(
                obs + (size_t)b * OBS_STRIDE + E_OFF + (size_t)(j * N_ + i) * S_ + q);
        }
        *reinterpret_cast<float4*>(&Es[slot * S_ + q]) = v;
    }
    __syncthreads();

    const int k = tid;
    float w1r[S_];
#pragma unroll
    for (int s = 0; s < S_; s++) w1r[s] = __ldg(&W1[s * H_ + k]);
    const float b1k = __ldg(&b1[k]);

#pragma unroll
    for (int e = 0; e < 16; e++) {
        float acc = b1k;
#pragma unroll
        for (int s = 0; s < S_; s++) acc += Es[e * S_ + s] * w1r[s];
        acc = (e < limit) ? fmaxf(acc, 0.0f) : 0.0f;
        __half h, l;
        hsplit(acc, h, l);
        const size_t o = (size_t)(base + e) * H_ + k;
        g_h1hi[o] = h;
        g_h1lo[o] = l;
    }
}

// ---------------------------------------------------------------------------
// shared MMA chunk body (K=32, ldmatrix, fp16 2-pass: (Ahi+Alo) @ Bh)
// ---------------------------------------------------------------------------
__device__ __forceinline__ void mma_chunk32(
    float acc[2][8][4], uint32_t stageBase, int warpM, int warpN, int lane) {
    const int lt = lane >> 3, lr = lane & 7;
    const uint32_t sAh = stageBase, sAl = stageBase + TILE_B;
    const uint32_t sBh = stageBase + 2 * TILE_B;
    uint32_t aOff[2];
#pragma unroll
    for (int m = 0; m < 2; m++) {
        const int row = warpM * 32 + m * 16 + ((lt & 1) << 3) + lr;
        aOff[m] = (uint32_t)(row * ASTR + ((lt >> 1) << 3)) * 2;
    }
    uint32_t bOff[4];
#pragma unroll
    for (int nb = 0; nb < 4; nb++) {
        const int n = warpN * 64 + nb * 16 + ((lt >> 1) << 3) + lr;
        bOff[nb] = (uint32_t)(n * ASTR + ((lt & 1) << 3)) * 2;
    }

#pragma unroll
    for (int kw = 0; kw < 32; kw += 16) {
        uint32_t ah[2][4], al[2][4];
#pragma unroll
        for (int m = 0; m < 2; m++) {
            LDSM_X4(ah[m][0], ah[m][1], ah[m][2], ah[m][3], sAh + aOff[m] + kw * 2);
            LDSM_X4(al[m][0], al[m][1], al[m][2], al[m][3], sAl + aOff[m] + kw * 2);
        }
#pragma unroll
        for (int nb = 0; nb < 4; nb++) {
            uint32_t bh[4];
            LDSM_X4(bh[0], bh[1], bh[2], bh[3], sBh + bOff[nb] + kw * 2);
#pragma unroll
            for (int m = 0; m < 2; m++) {
                MMA_F16(acc[m][2 * nb + 0], ah[m], bh[0], bh[1]);
                MMA_F16(acc[m][2 * nb + 0], al[m], bh[0], bh[1]);
                MMA_F16(acc[m][2 * nb + 1], ah[m], bh[2], bh[3]);
                MMA_F16(acc[m][2 * nb + 1], al[m], bh[2], bh[3]);
            }
        }
    }
}

// ---------------------------------------------------------------------------
// G1: h2 = relu(h1 @ W2T^T + b2); cp.async double-buffered, K-chunk 32 (8 ch)
// grid (512 tiles, 2 col-tiles), 256 thr = 8 warps (4Mx2N)
// ---------------------------------------------------------------------------
__global__ void __launch_bounds__(256, 2) g1_mma_kernel(const float* __restrict__ b2) {
    extern __shared__ __align__(16) __half smem[];
    const int tile = blockIdx.x;
    if (tile >= g_meta[2]) return;
    const int c0 = blockIdx.y * 128;
    const int tid = threadIdx.x, wid = tid >> 5, lane = tid & 31;
    const int warpM = wid & 3, warpN = wid >> 2;
    const int g = lane >> 2, tig = lane & 3;
    const uint32_t sb = smem_u32(smem);
    const size_t abase = (size_t)tile * 128 * H_;

    auto load = [&](int ch, int st) {
        const int k0 = ch * 32;
        const uint32_t sbase = sb + st * STAGE_B;
#pragma unroll
        for (int l = 0; l < 2; l++) {
            const int cc = l * 256 + tid;       // 0..511
            const int r = cc >> 2, kq = (cc & 3) * 8;
            const uint32_t d = sbase + (uint32_t)(r * ASTR + kq) * 2;
            CP16(d + 0 * TILE_B, g_h1hi + abase + (size_t)r * H_ + k0 + kq);
            CP16(d + 1 * TILE_B, g_h1lo + abase + (size_t)r * H_ + k0 + kq);
            CP16(d + 2 * TILE_B, g_W2Th + (size_t)(c0 + r) * H_ + k0 + kq);
        }
    };

    float acc[2][8][4];
#pragma unroll
    for (int m = 0; m < 2; m++)
#pragma unroll
        for (int n = 0; n < 8; n++)
#pragma unroll
            for (int q = 0; q < 4; q++) acc[m][n][q] = 0.0f;

    load(0, 0);
    CP_COMMIT();
    int stage = 0;
#pragma unroll 1
    for (int ch = 0; ch < 8; ch++) {
        if (ch + 1 < 8) {
            load(ch + 1, stage ^ 1);
            CP_COMMIT();
            CP_WAIT(1);
        } else {
            CP_WAIT(0);
        }
        __syncthreads();
        mma_chunk32(acc, sb + stage * STAGE_B, warpM, warpN, lane);
        __syncthreads();
        stage ^= 1;
    }

#pragma unroll
    for (int n = 0; n < 8; n++) {
        const int col = c0 + warpN * 64 + n * 8 + tig * 2;
        const float bias0 = __ldg(&b2[col]), bias1 = __ldg(&b2[col + 1]);
#pragma unroll
        for (int m = 0; m < 2; m++) {
            const int r0 = tile * 128 + warpM * 32 + m * 16 + g;
            float2 v0 = make_float2(fmaxf(acc[m][n][0] + bias0, 0.0f),
                                    fmaxf(acc[m][n][1] + bias1, 0.0f));
            float2 v1 = make_float2(fmaxf(acc[m][n][2] + bias0, 0.0f),
                                    fmaxf(acc[m][n][3] + bias1, 0.0f));
            *reinterpret_cast<float2*>(&g_h2[(size_t)r0 * H_ + col]) = v0;
            *reinterpret_cast<float2*>(&g_h2[(size_t)(r0 + 8) * H_ + col]) = v1;
        }
    }
}

// ---------------------------------------------------------------------------
// fold: A2[row] = [ M(h,f) | sumX (bk) | X (Wroot) | 1 (bconv) | 0 ]
// grid 2048 rows, 256 thr (thread = h); 4-wide h2 prefetch
// ---------------------------------------------------------------------------
__global__ void __launch_bounds__(256) fold_kernel(const float* __restrict__ obs) {
    __shared__ float Xs[N_ * F_];
    __shared__ int idx[N_];
    __shared__ int s_start, s_cnt;
    const int row = blockIdx.x;
    const int b = row >> 5, j = row & 31;
    const int k = threadIdx.x;
    const float* orow = obs + (size_t)b * OBS_STRIDE;

    if (k == 0) {
        s_start = g_rowStart[row];
        s_cnt = g_cnt[row];
    }
    for (int t = k; t < N_ * F_; t += 256) Xs[t] = orow[t];
    __syncthreads();
    const int cnt = s_cnt, start = s_start;
    if (k < cnt) idx[k] = g_eSrc[start + k];
    __syncthreads();

    float M[F_];
#pragma unroll
    for (int f = 0; f < F_; f++) M[f] = 0.0f;

    const float* h2p = g_h2 + (size_t)start * H_ + k;
    int e = 0;
    for (; e + 4 <= cnt; e += 4) {
        const float v0 = h2p[(size_t)(e + 0) * H_];
        const float v1 = h2p[(size_t)(e + 1) * H_];
        const float v2 = h2p[(size_t)(e + 2) * H_];
        const float v3 = h2p[(size_t)(e + 3) * H_];
        const int i0 = idx[e], i1 = idx[e + 1], i2 = idx[e + 2], i3 = idx[e + 3];
#pragma unroll
        for (int f = 0; f < F_; f++) {
            M[f] += v0 * Xs[i0 * F_ + f];
            M[f] += v1 * Xs[i1 * F_ + f];
            M[f] += v2 * Xs[i2 * F_ + f];
            M[f] += v3 * Xs[i3 * F_ + f];
        }
    }
    for (; e < cnt; e++) {
        const float h2v = h2p[(size_t)e * H_];
        const int i = idx[e];
#pragma unroll
        for (int f = 0; f < F_; f++) M[f] += h2v * Xs[i * F_ + f];
    }

    __align__(16) __half hi[F_], lo[F_];
#pragma unroll
    for (int f = 0; f < F_; f++) hsplit(M[f], hi[f], lo[f]);
    {
        const size_t o = (size_t)row * KAUG2 + k * F_;
        reinterpret_cast<uint4*>(g_A2hi + o)[0] = reinterpret_cast<uint4*>(hi)[0];
        reinterpret_cast<uint4*>(g_A2hi + o)[1] = reinterpret_cast<uint4*>(hi)[1];
        reinterpret_cast<uint4*>(g_A2lo + o)[0] = reinterpret_cast<uint4*>(lo)[0];
        reinterpret_cast<uint4*>(g_A2lo + o)[1] = reinterpret_cast<uint4*>(lo)[1];
    }

    // augmented tail: sumX (kk 4096..4111), X (4112..4127), 1.0 (4128), 0 pad
    if (k < 16) {
        float ssum = 0.0f;
        for (int ee = 0; ee < cnt; ee++) ssum += Xs[idx[ee] * F_ + k];
        __half h, l;
        hsplit(ssum, h, l);
        g_A2hi[(size_t)row * KAUG2 + 4096 + k] = h;
        g_A2lo[(size_t)row * KAUG2 + 4096 + k] = l;
    } else if (k < 32) {
        __half h, l;
        hsplit(Xs[j * F_ + (k - 16)], h, l);
        g_A2hi[(size_t)row * KAUG2 + 4096 + k] = h;
        g_A2lo[(size_t)row * KAUG2 + 4096 + k] = l;
    } else if (k == 32) {
        g_A2hi[(size_t)row * KAUG2 + 4128] = __float2half(1.0f);
        g_A2lo[(size_t)row * KAUG2 + 4128] = __float2half(0.0f);
    } else if (k < 64) {
        g_A2hi[(size_t)row * KAUG2 + 4096 + k] = __float2half(0.0f);
        g_A2lo[(size_t)row * KAUG2 + 4096 + k] = __float2half(0.0f);
    }
}

// ---------------------------------------------------------------------------
// G2: P[s] partial of A2[2048,4160] @ B2^T; cp.async double-buffered, K-chunk 32
// grid (16 row-tiles, 16 splits) = 256 CTAs, 2 CTAs/SM
// ---------------------------------------------------------------------------
__global__ void __launch_bounds__(256, 2) g2_mma_kernel() {
    extern __shared__ __align__(16) __half smem[];
    const int r0 = blockIdx.x * 128;
    const int s = blockIdx.y;
    const int tid = threadIdx.x, wid = tid >> 5, lane = tid & 31;
    const int warpM = wid & 3, warpN = wid >> 2;
    const int g = lane >> 2, tig = lane & 3;
    const uint32_t sb = smem_u32(smem);

    auto load = [&](int ch, int st) {
        const int k0 = ch * 32;
        const uint32_t sbase = sb + st * STAGE_B;
#pragma unroll
        for (int l = 0; l < 2; l++) {
            const int cc = l * 256 + tid;
            const int r = cc >> 2, kq = (cc & 3) * 8;
            const uint32_t d = sbase + (uint32_t)(r * ASTR + kq) * 2;
            CP16(d + 0 * TILE_B, g_A2hi + (size_t)(r0 + r) * KAUG2 + k0 + kq);
            CP16(d + 1 * TILE_B, g_A2lo + (size_t)(r0 + r) * KAUG2 + k0 + kq);
            CP16(d + 2 * TILE_B, g_B2h + (size_t)r * KAUG2 + k0 + kq);
        }
    };

    float acc[2][8][4];
#pragma unroll
    for (int m = 0; m < 2; m++)
#pragma unroll
        for (int n = 0; n < 8; n++)
#pragma unroll
            for (int q = 0; q < 4; q++) acc[m][n][q] = 0.0f;

    int ch = s;
    load(ch, 0);
    CP_COMMIT();
    int stage = 0;
#pragma unroll 1
    while (true) {
        const int chn = ch + KSPLIT;
        const bool more = (chn < KCH2);
        if (more) {
            load(chn, stage ^ 1);
            CP_COMMIT();
            CP_WAIT(1);
        } else {
            CP_WAIT(0);
        }
        __syncthreads();
        mma_chunk32(acc, sb + stage * STAGE_B, warpM, warpN, lane);
        if (!more) break;
        __syncthreads();
        ch = chn;
        stage ^= 1;
    }

#pragma unroll
    for (int n = 0; n < 8; n++) {
        const int col = warpN * 64 + n * 8 + tig * 2;
#pragma unroll
        for (int m = 0; m < 2; m++) {
            const int rr = r0 + warpM * 32 + m * 16 + g;
            float2 v0 = make_float2(acc[m][n][0], acc[m][n][1]);
            float2 v1 = make_float2(acc[m][n][2], acc[m][n][3]);
            *reinterpret_cast<float2*>(&g_P[((size_t)s * ROWS + rr) * C_ + col]) = v0;
            *reinterpret_cast<float2*>(&g_P[((size_t)s * ROWS + rr + 8) * C_ + col]) = v1;
        }
    }
}

// ---------------------------------------------------------------------------
// phase3: reduce splits -> Xc (relu), attention softmax pool, dense tanh
// ---------------------------------------------------------------------------
__global__ void __launch_bounds__(256) phase3_kernel(
    const float* __restrict__ attn_w,
    const float* __restrict__ Wd,
    const float* __restrict__ bd,
    float* __restrict__ out) {
    __shared__ __align__(16) float Xc[N_][C_];
    __shared__ float attn[N_];
    __shared__ float logits[N_];
    __shared__ float pooled[C_];

    const int b = blockIdx.x;
    const int tid = threadIdx.x;

    for (int t = tid; t < N_ * C_; t += 256) {
        const int j = t >> 7, c = t & 127;
        const int row = b * N_ + j;
        float sum = 0.0f;
#pragma unroll
        for (int s = 0; s < KSPLIT; s++)
            sum += g_P[((size_t)s * ROWS + row) * C_ + c];
        Xc[j][c] = fmaxf(sum, 0.0f);
    }
    __syncthreads();

    const int w = tid >> 5, lane = tid & 31;
    const float aw0 = attn_w[lane], aw1 = attn_w[lane + 32];
    const float aw2 = attn_w[lane + 64], aw3 = attn_w[lane + 96];
    for (int j = w * 4; j < w * 4 + 4; j++) {
        float p = Xc[j][lane] * aw0 + Xc[j][lane + 32] * aw1 +
                  Xc[j][lane + 64] * aw2 + Xc[j][lane + 96] * aw3;
#pragma unroll
        for (int off = 16; off; off >>= 1) p += __shfl_xor_sync(0xffffffffu, p, off);
        if (lane == 0) logits[j] = p;
    }
    __syncthreads();

    if (tid < 32) {
        float l = logits[tid];
        float m = l;
#pragma unroll
        for (int off = 16; off; off >>= 1)
            m = fmaxf(m, __shfl_xor_sync(0xffffffffu, m, off));
        float e = expf(l - m);
        float ssum = e;
#pragma unroll
        for (int off = 16; off; off >>= 1) ssum += __shfl_xor_sync(0xffffffffu, ssum, off);
        attn[tid] = e / ssum;
    }
    __syncthreads();

    if (tid < C_) {
        float pc = 0.0f;
#pragma unroll
        for (int j = 0; j < N_; j++) pc += attn[j] * Xc[j][tid];
        pooled[tid] = pc;
    }
    __syncthreads();

    float sum = bd[tid];
#pragma unroll 8
    for (int cc = 0; cc < C_; cc++) sum += pooled[cc] * Wd[cc * D_ + tid];
    out[(size_t)b * D_ + tid] = tanhf(sum);
}

// ---------------------------------------------------------------------------
extern "C" void kernel_launch(void* const* d_in, const int* in_sizes, int n_in,
                              void* d_out, int out_size) {
    const float* obs    = (const float*)d_in[0];
    const float* W1     = (const float*)d_in[1];
    const float* b1     = (const float*)d_in[2];
    const float* W2     = (const float*)d_in[3];
    const float* b2     = (const float*)d_in[4];
    const float* Wk     = (const float*)d_in[5];
    const float* bk     = (const float*)d_in[6];
    const float* Wroot  = (const float*)d_in[7];
    const float* bconv  = (const float*)d_in[8];
    const float* attn_w = (const float*)d_in[9];
    const float* Wd     = (const float*)d_in[10];
    const float* bd     = (const float*)d_in[11];
    float* out = (float*)d_out;

    cudaFuncSetAttribute(g1_mma_kernel,
                         cudaFuncAttributeMaxDynamicSharedMemorySize, MMA_SMEM_BYTES);
    cudaFuncSetAttribute(g2_mma_kernel,
                         cudaFuncAttributeMaxDynamicSharedMemorySize, MMA_SMEM_BYTES);

    prep_kernel<<<(C_ * KAUG2 + 255) / 256, 256>>>(W2, Wk, bk, Wroot, bconv);
    count_scan_kernel<<<1, 1024>>>(obs);
    fill_kernel<<<B_, 256>>>(obs);
    h1_kernel<<<dim3(512, 8), 256>>>(obs, W1, b1);
    g1_mma_kernel<<<dim3(512, 2), 256, MMA_SMEM_BYTES>>>(b2);
    fold_kernel<<<ROWS, 256>>>(obs);
    g2_mma_kernel<<<dim3(16, KSPLIT), 256, MMA_SMEM_BYTES>>>();
    phase3_kernel<<<B_, 256>>>(attn_w, Wd, bd, out);
}